// round 14
// baseline (speedup 1.0000x reference)
#include <cuda_runtime.h>
#include <math.h>
#include <stdint.h>

#define TT 34
#define NV 14
#define NROW (TT * NV)      // 476
#define LT 40               // transposed L-table row stride (floats)

typedef unsigned long long u64;

// -------- fast approx intrinsics -----
__device__ __forceinline__ float fexp2(float x) {
    float r; asm("ex2.approx.f32 %0, %1;" : "=f"(r) : "f"(x)); return r;
}
__device__ __forceinline__ float frsq(float x) {
    float r; asm("rsqrt.approx.f32 %0, %1;" : "=f"(r) : "f"(x)); return r;
}
__device__ __forceinline__ float frcp(float x) {
    float r; asm("rcp.approx.f32 %0, %1;" : "=f"(r) : "f"(x)); return r;
}

// -------- packed f32x2 (epilogue only — fenced behind noinline) --------
#define MUL2(d,a,b)   asm("mul.rn.f32x2 %0, %1, %2;" : "=l"(d) : "l"(a), "l"(b))
#define FMA2(d,a,b,c) asm("fma.rn.f32x2 %0, %1, %2, %3;" : "=l"(d) : "l"(a), "l"(b), "l"(c))
__device__ __forceinline__ u64 pk2(float lo, float hi) {
    u64 d; asm("mov.b64 %0, {%1, %2};" : "=l"(d) : "r"(__float_as_uint(lo)), "r"(__float_as_uint(hi)));
    return d;
}

// ----------------------------------------------------------------------------
// Epilogue for ONE t. Attention state (a0,a1,den) in u-space; tp = t*16 + a.
// sc: [0..9] G (2x5 fold of V^T@out_A@out_B) | [28+j*16+v] W' | [108..117] F1
//     [118..119] fc1_b | [120..129] fc2_w | [130..134] fc2_b
// ----------------------------------------------------------------------------
__device__ __forceinline__ void epi_one(
    const float* __restrict__ sc, const float* __restrict__ sxa,
    const float* __restrict__ spos,
    float a0, float a1, float den, int tp, float* __restrict__ ob)
{
    const int t = tp >> 4, a = tp & 15;
    float x0 = sxa[a*2], x1 = sxa[a*2+1];
    float x2 = spos[t*4], x3 = spos[t*4+1], x4 = spos[t*4+2];

    float inv = frcp(den);
    float A0 = a0 * inv, A1 = a1 * inv;

    float y0 = x0 + A0*sc[0] + A1*sc[5];
    float y1 = x1 + A0*sc[1] + A1*sc[6];
    float y2 = x2 + A0*sc[2] + A1*sc[7];
    float y3 = x3 + A0*sc[3] + A1*sc[8];
    float y4 = x4 + A0*sc[4] + A1*sc[9];

    float r2 = frsq((y0*y0 + y1*y1 + y2*y2 + y3*y3 + y4*y4) * 0.2f + 1e-5f);

    float g0 = fmaf(r2, y0*sc[108] + y1*sc[109] + y2*sc[110] + y3*sc[111] + y4*sc[112], sc[118]);
    float g1 = fmaf(r2, y0*sc[113] + y1*sc[114] + y2*sc[115] + y3*sc[116] + y4*sc[117], sc[119]);

    const float isq2 = 0.70710678118654752f;
    float e0 = 0.5f * g0 * (1.0f + erff(g0 * isq2));
    float e1 = 0.5f * g1 * (1.0f + erff(g1 * isq2));

    float z0 = y0 + sc[130] + e0*sc[120] + e1*sc[121];
    float z1 = y1 + sc[131] + e0*sc[122] + e1*sc[123];
    float z2 = y2 + sc[132] + e0*sc[124] + e1*sc[125];
    float z3 = y3 + sc[133] + e0*sc[126] + e1*sc[127];
    float z4 = y4 + sc[134] + e0*sc[128] + e1*sc[129];

    float rf = frsq((z0*z0 + z1*z1 + z2*z2 + z3*z3 + z4*z4) * 0.2f + 1e-5f);

    u64 zz0 = pk2(z0*rf, z0*rf), zz1 = pk2(z1*rf, z1*rf);
    u64 zz2 = pk2(z2*rf, z2*rf), zz3 = pk2(z3*rf, z3*rf);
    u64 zz4 = pk2(z4*rf, z4*rf);
    const u64* w0 = reinterpret_cast<const u64*>(sc + 28);
    const u64* w1 = reinterpret_cast<const u64*>(sc + 44);
    const u64* w2 = reinterpret_cast<const u64*>(sc + 60);
    const u64* w3 = reinterpret_cast<const u64*>(sc + 76);
    const u64* w4 = reinterpret_cast<const u64*>(sc + 92);
    u64* ob64 = reinterpret_cast<u64*>(ob);
#pragma unroll
    for (int vp = 0; vp < 7; vp++) {
        u64 acc;
        MUL2(acc, zz0, w0[vp]);
        FMA2(acc, zz1, w1[vp], acc);
        FMA2(acc, zz2, w2[vp], acc);
        FMA2(acc, zz3, w3[vp], acc);
        FMA2(acc, zz4, w4[vp], acc);
        ob64[vp] = acc;
    }
}

// Pair epilogue: two consecutive t's -> 28 contiguous floats -> 7x STG.128.
__device__ __noinline__ void do_epilogue_pair(
    const float* __restrict__ sc, const float* __restrict__ sxa,
    const float* __restrict__ spos,
    float a00, float a01, float d0, int tp0,
    float a10, float a11, float d1, int tp1,
    float* __restrict__ op)
{
    __align__(16) float ob[28];
    epi_one(sc, sxa, spos, a00, a01, d0, tp0, ob);
    epi_one(sc, sxa, spos, a10, a11, d1, tp1, ob + 14);
    float4* dst = reinterpret_cast<float4*>(op);
    const float4* src = reinterpret_cast<const float4*>(ob);
#pragma unroll
    for (int i = 0; i < 7; i++)
        dst[i] = src[i];
}

// per-pair update (wls_j = L[s][t_j] * w_s precomputed per row)
#define PAIR_UPDATE(j, WLS)                                                    \
    {                                                                          \
        float e = fexp2(w_t[j] * (WLS));                                       \
        den[j]  += e;                                                          \
        acc0[j] = fmaf(e, wu.y, acc0[j]);                                      \
        acc1[j] = fmaf(e, wu.z, acc1[j]);                                      \
    }

// load one s-row: per-thread wu (rr,u0,u1) + warp-uniform L block
#define LOAD_ROW(sidx, c, tcol)                                                \
    float4 wu = *reinterpret_cast<const float4*>(s_wu + (((sidx)*NV)+(c))*4);  \
    const float* Lr = s_L + (sidx)*LT + (tcol);                                \
    float4 L0 = *reinterpret_cast<const float4*>(Lr);                          \
    float4 L1 = *reinterpret_cast<const float4*>(Lr + 4);                      \
    float wls0 = L0.x*wu.x, wls1 = L0.y*wu.x, wls2 = L0.z*wu.x, wls3 = L0.w*wu.x; \
    float wls4 = L1.x*wu.x, wls5 = L1.y*wu.x, wls6 = L1.z*wu.x, wls7 = L1.w*wu.x;

__global__ __launch_bounds__(256, 2) void micro_tf_kernel(
    const int*   __restrict__ idx,
    const float* __restrict__ tok_emb,
    const float* __restrict__ p_amp,   const float* __restrict__ p_phase,
    const float* __restrict__ p_slope, const float* __restrict__ p_offset,
    const float* __restrict__ p_cs,    const float* __restrict__ p_ci,
    const float* __restrict__ z_hi,    const float* __restrict__ special,
    const float* __restrict__ q_w,     const float* __restrict__ v_w,
    const float* __restrict__ out_A,   const float* __restrict__ out_B,
    const float* __restrict__ q_phase,
    const float* __restrict__ ln1_w,   const float* __restrict__ ln2_w,
    const float* __restrict__ lnf_w,
    const float* __restrict__ fc1_w,   const float* __restrict__ fc1_b,
    const float* __restrict__ fc2_w,   const float* __restrict__ fc2_b,
    const float* __restrict__ head_w,
    float* __restrict__ out, int B, int bpc)
{
    __shared__ __align__(16) float s_wu[NROW * 4];   // {rr, u0, u1, 0} per (s,a)
    __shared__ __align__(16) float s_L[TT * LT];     // L[s][t] transposed, pre-scaled
    __shared__ __align__(16) float s_pos[TT * 4];
    __shared__ float s_xa[NV * 2];
    __shared__ float s_qh[TT * 5];
    __shared__ float s_qr[TT * 5];
    __shared__ __align__(16) float s_c[152];

    const int tid = threadIdx.x;

    // ---- stage A: per-t pos / q-hat / q-hat-rot ----
    if (tid < TT) {
        const int t = tid;
        float p0, p1, p2;
        if (t == 33)      { p0 = 0.f;        p1 = 0.f;        p2 = 0.f; }
        else if (t == 32) { p0 = z_hi[0];    p1 = z_hi[1];    p2 = z_hi[2]; }
        else if (t == 10) { p0 = special[0]; p1 = special[1]; p2 = special[2]; }
        else if (t == 21) { p0 = special[3]; p1 = special[4]; p2 = special[5]; }
        else {
            int i = (t < 10) ? t : ((t < 21) ? t - 11 : t - 22);
            float fi  = (float)i;
            float ang = 0.62831853071795864f * fi + p_phase[0];
            float amp = p_amp[0];
            float b0 = amp * cosf(ang);
            float b1 = amp * sinf(ang);
            float b2 = p_slope[0] * fi + p_offset[0];
            float m  = 1.0f + p_ci[0] + p_cs[0] * fi;
            p0 = b0 * m; p1 = b1 * m; p2 = b2 * m;
        }
        s_pos[t*4] = p0; s_pos[t*4+1] = p1; s_pos[t*4+2] = p2; s_pos[t*4+3] = 0.f;

        float hp0 = p0 * ln1_w[2], hp1 = p1 * ln1_w[3], hp2 = p2 * ln1_w[4];
        float qh[5];
#pragma unroll
        for (int d = 0; d < 5; d++)
            qh[d] = hp0*q_w[d*3] + hp1*q_w[d*3+1] + hp2*q_w[d*3+2];
        float cc = cosf(q_phase[0]), ss = sinf(q_phase[0]);
        s_qh[t*5+0] = qh[0]; s_qh[t*5+1] = qh[1]; s_qh[t*5+2] = qh[2];
        s_qh[t*5+3] = qh[3]; s_qh[t*5+4] = qh[4];
        s_qr[t*5+0] = qh[0]*cc - qh[1]*ss;
        s_qr[t*5+1] = qh[0]*ss + qh[1]*cc;
        s_qr[t*5+2] = qh[2]*cc - qh[3]*ss;
        s_qr[t*5+3] = qh[2]*ss + qh[3]*cc;
        s_qr[t*5+4] = qh[4];
    }
    if (tid < NV * 2) s_xa[tid] = tok_emb[tid];

    if (tid == 0) {
        // G[c][j] = sum_d v_w[d*2+c] * (out_A@out_B)[d][j]
        float M1[25];
        for (int d = 0; d < 5; d++)
            for (int j = 0; j < 5; j++)
                M1[d*5 + j] = out_A[d*2]*out_B[j] + out_A[d*2+1]*out_B[5+j];
        for (int c = 0; c < 2; c++)
            for (int j = 0; j < 5; j++) {
                float g = 0.f;
                for (int d = 0; d < 5; d++) g += v_w[d*2 + c] * M1[d*5 + j];
                s_c[c*5 + j] = g;
            }
        for (int j = 0; j < 5; j++)
            for (int v = 0; v < NV; v++)
                s_c[28 + j*16 + v] =
                    lnf_w[j] * (head_w[j]*tok_emb[v*2] + head_w[5+j]*tok_emb[v*2+1]);
        for (int f = 0; f < 2; f++)
            for (int j = 0; j < 5; j++)
                s_c[108 + f*5 + j] = fc1_w[f*5 + j] * ln2_w[j];
        s_c[118] = fc1_b[0]; s_c[119] = fc1_b[1];
        for (int d = 0; d < 5; d++) {
            s_c[120 + d*2]     = fc2_w[d*2];
            s_c[120 + d*2 + 1] = fc2_w[d*2 + 1];
            s_c[130 + d]       = fc2_b[d];
        }
    }
    __syncthreads();

    // ---- stage B: wu per (s,a) ----
    for (int r = tid; r < TT * NV; r += 256) {
        int t = r / NV, a = r % NV;
        float x0 = s_xa[a*2], x1 = s_xa[a*2+1];
        float p0 = s_pos[t*4], p1 = s_pos[t*4+1], p2 = s_pos[t*4+2];
        float ms = (x0*x0 + x1*x1 + p0*p0 + p1*p1 + p2*p2) * 0.2f;
        float rr = rsqrtf(ms + 1e-5f);
        s_wu[r*4]   = rr;
        s_wu[r*4+1] = rr * x0 * ln1_w[0];
        s_wu[r*4+2] = rr * x1 * ln1_w[1];
        s_wu[r*4+3] = 0.f;
    }

    // ---- stage C: transposed L[s][t] = ksc * qr(t).qh(s) ----
    const float ksc = 1.4426950408889634f * 0.44721359549995794f; // log2e/sqrt5
    for (int r = tid; r < TT * TT; r += 256) {
        int s = r / TT, t = r % TT;
        float l = s_qr[t*5]*s_qh[s*5] + s_qr[t*5+1]*s_qh[s*5+1]
                + s_qr[t*5+2]*s_qh[s*5+2] + s_qr[t*5+3]*s_qh[s*5+3]
                + s_qr[t*5+4]*s_qh[s*5+4];
        s_L[s*LT + t] = l * ksc;
    }
    __syncthreads();

    // balanced assignment: every CTA handles bpc rows; 296 CTAs = 2 per SM
    const int b = blockIdx.x * bpc + tid;
    if (tid >= bpc || b >= B) return;

    // ---- pack this row's 34 tokens, 4 bits each ----
    uint32_t pk[5] = {0u, 0u, 0u, 0u, 0u};
    const int2* ip2 = reinterpret_cast<const int2*>(idx + (size_t)b * TT);
#pragma unroll
    for (int w = 0; w < 17; w++) {
        int2 tv = __ldg(ip2 + w);
        const int s0 = 2*w, s1 = 2*w + 1;
        pk[s0 >> 3] |= ((uint32_t)tv.x) << ((s0 & 7) * 4);
        pk[s1 >> 3] |= ((uint32_t)tv.y) << ((s1 & 7) * 4);
    }

    float* obase = out + (size_t)b * (TT * NV);

    float w_t[8], acc0[8], acc1[8], den[8];

#pragma unroll
    for (int k = 0; k < 5; k++) {
        const int nt = (k == 4) ? 2 : 8;
        const uint32_t tb = pk[k];
        const int tcol = 8 * k;

        // per-tile query weights, zero accumulators
#pragma unroll
        for (int j = 0; j < 8; j++) {
            if (j < nt) {
                int a = (tb >> (4*j)) & 15;
                w_t[j] = s_wu[(((tcol + j) * NV) + a) * 4];
                den[j] = 0.f; acc0[j] = 0.f; acc1[j] = 0.f;
            }
        }

        // phase 1: full octets s in [0, 8k)
#pragma unroll
        for (int w = 0; w < k; w++) {
            uint32_t bits = pk[w];
#pragma unroll 1
            for (int jj = 0; jj < 8; jj++) {
                int c = bits & 15; bits >>= 4;
                LOAD_ROW(w*8 + jj, c, tcol)
                if (nt == 8) {
                    PAIR_UPDATE(0, wls0) PAIR_UPDATE(1, wls1)
                    PAIR_UPDATE(2, wls2) PAIR_UPDATE(3, wls3)
                    PAIR_UPDATE(4, wls4) PAIR_UPDATE(5, wls5)
                    PAIR_UPDATE(6, wls6) PAIR_UPDATE(7, wls7)
                } else {
                    PAIR_UPDATE(0, wls0) PAIR_UPDATE(1, wls1)
                    (void)wls2; (void)wls3; (void)wls4;
                    (void)wls5; (void)wls6; (void)wls7;
                }
            }
        }

        // phase 2: triangular, s = 8k + s2 (query j active iff j >= s2)
        {
            uint32_t bits = tb;
#pragma unroll
            for (int s2 = 0; s2 < 8; s2++) {
                if (s2 < nt) {
                    int c = bits & 15;
                    LOAD_ROW(tcol + s2, c, tcol)
                    if (s2 <= 0 && 0 < nt) PAIR_UPDATE(0, wls0)
                    if (s2 <= 1 && 1 < nt) PAIR_UPDATE(1, wls1)
                    if (s2 <= 2 && 2 < nt) PAIR_UPDATE(2, wls2)
                    if (s2 <= 3 && 3 < nt) PAIR_UPDATE(3, wls3)
                    if (s2 <= 4 && 4 < nt) PAIR_UPDATE(4, wls4)
                    if (s2 <= 5 && 5 < nt) PAIR_UPDATE(5, wls5)
                    if (s2 <= 6 && 6 < nt) PAIR_UPDATE(6, wls6)
                    if (s2 <= 7 && 7 < nt) PAIR_UPDATE(7, wls7)
                }
                bits >>= 4;
            }
        }

        // epilogue per pair of t's (noinline) -> 7x STG.128 per pair
#pragma unroll
        for (int jp = 0; jp < 4; jp++) {
            const int j0 = 2*jp, j1 = 2*jp + 1;
            if (j0 < nt) {
                int t0 = tcol + j0, t1 = tcol + j1;
                int a0 = (tb >> (4*j0)) & 15;
                int a1 = (tb >> (4*j1)) & 15;
                do_epilogue_pair(s_c, s_xa, s_pos,
                    acc0[j0], acc1[j0], den[j0], t0*16 + a0,
                    acc0[j1], acc1[j1], den[j1], t1*16 + a1,
                    obase + t0 * NV);
            }
        }
    }
}

extern "C" void kernel_launch(void* const* d_in, const int* in_sizes, int n_in,
                              void* d_out, int out_size)
{
    const int*   idx     = (const int*)  d_in[0];
    const float* tok_emb = (const float*)d_in[1];
    const float* amp     = (const float*)d_in[2];
    const float* phase   = (const float*)d_in[3];
    const float* slope   = (const float*)d_in[4];
    const float* offset  = (const float*)d_in[5];
    const float* cslope  = (const float*)d_in[6];
    const float* cicept  = (const float*)d_in[7];
    const float* z_hi    = (const float*)d_in[8];
    const float* special = (const float*)d_in[9];
    const float* q_w     = (const float*)d_in[10];
    const float* v_w     = (const float*)d_in[11];
    const float* out_A   = (const float*)d_in[12];
    const float* out_B   = (const float*)d_in[13];
    const float* q_phase = (const float*)d_in[14];
    const float* ln1_w   = (const float*)d_in[15];
    const float* ln2_w   = (const float*)d_in[16];
    const float* lnf_w   = (const float*)d_in[17];
    const float* fc1_w   = (const float*)d_in[18];
    const float* fc1_b   = (const float*)d_in[19];
    const float* fc2_w   = (const float*)d_in[20];
    const float* fc2_b   = (const float*)d_in[21];
    const float* head_w  = (const float*)d_in[22];
    float* out = (float*)d_out;

    const int B = in_sizes[0] / TT;

    // balanced grid: 296 CTAs = exactly 2 per SM on 148-SM GB300
    const int NCTA = 296;
    int bpc = (B + NCTA - 1) / NCTA;            // rows per CTA (<= 256)
    if (bpc > 256) bpc = 256;                   // safety: fall back pattern
    const int grid = (B + bpc - 1) / bpc;

    micro_tf_kernel<<<grid, 256>>>(
        idx, tok_emb, amp, phase, slope, offset, cslope, cicept,
        z_hi, special, q_w, v_w, out_A, out_B, q_phase,
        ln1_w, ln2_w, lnf_w, fc1_w, fc1_b, fc2_w, fc2_b, head_w,
        out, B, bpc);
}

// round 15
// speedup vs baseline: 1.0042x; 1.0042x over previous
#include <cuda_runtime.h>
#include <math.h>
#include <stdint.h>

#define TT 34
#define NV 14
#define NROW (TT * NV)      // 476
#define LT 40               // transposed L-table row stride (floats)

// -------- fast approx intrinsics -----
__device__ __forceinline__ float fexp2(float x) {
    float r; asm("ex2.approx.f32 %0, %1;" : "=f"(r) : "f"(x)); return r;
}
__device__ __forceinline__ float frsq(float x) {
    float r; asm("rsqrt.approx.f32 %0, %1;" : "=f"(r) : "f"(x)); return r;
}
__device__ __forceinline__ float frcp(float x) {
    float r; asm("rcp.approx.f32 %0, %1;" : "=f"(r) : "f"(x)); return r;
}

// ----------------------------------------------------------------------------
// Epilogue for ONE t (scalar — minimal register footprint). tp = t*16 + a.
// sc: [0..9] G (2x5 fold of V^T@out_A@out_B) | [28+j*16+v] W' | [108..117] F1
//     [118..119] fc1_b | [120..129] fc2_w | [130..134] fc2_b
// ----------------------------------------------------------------------------
__device__ __forceinline__ void epi_one(
    const float* __restrict__ sc, const float* __restrict__ sxa,
    const float* __restrict__ spos,
    float a0, float a1, float den, int tp, float* __restrict__ ob)
{
    const int t = tp >> 4, a = tp & 15;
    float x0 = sxa[a*2], x1 = sxa[a*2+1];
    float x2 = spos[t*4], x3 = spos[t*4+1], x4 = spos[t*4+2];

    float inv = frcp(den);
    float A0 = a0 * inv, A1 = a1 * inv;

    float y0 = x0 + A0*sc[0] + A1*sc[5];
    float y1 = x1 + A0*sc[1] + A1*sc[6];
    float y2 = x2 + A0*sc[2] + A1*sc[7];
    float y3 = x3 + A0*sc[3] + A1*sc[8];
    float y4 = x4 + A0*sc[4] + A1*sc[9];

    float r2 = frsq((y0*y0 + y1*y1 + y2*y2 + y3*y3 + y4*y4) * 0.2f + 1e-5f);

    float g0 = fmaf(r2, y0*sc[108] + y1*sc[109] + y2*sc[110] + y3*sc[111] + y4*sc[112], sc[118]);
    float g1 = fmaf(r2, y0*sc[113] + y1*sc[114] + y2*sc[115] + y3*sc[116] + y4*sc[117], sc[119]);

    const float isq2 = 0.70710678118654752f;
    float e0 = 0.5f * g0 * (1.0f + erff(g0 * isq2));
    float e1 = 0.5f * g1 * (1.0f + erff(g1 * isq2));

    float z0 = y0 + sc[130] + e0*sc[120] + e1*sc[121];
    float z1 = y1 + sc[131] + e0*sc[122] + e1*sc[123];
    float z2 = y2 + sc[132] + e0*sc[124] + e1*sc[125];
    float z3 = y3 + sc[133] + e0*sc[126] + e1*sc[127];
    float z4 = y4 + sc[134] + e0*sc[128] + e1*sc[129];

    float rf = frsq((z0*z0 + z1*z1 + z2*z2 + z3*z3 + z4*z4) * 0.2f + 1e-5f);
    z0 *= rf; z1 *= rf; z2 *= rf; z3 *= rf; z4 *= rf;

#pragma unroll
    for (int v = 0; v < NV; v++) {
        ob[v] = z0*sc[28 + v] + z1*sc[44 + v] + z2*sc[60 + v]
              + z3*sc[76 + v] + z4*sc[92 + v];
    }
}

// Pair epilogue: two consecutive t's -> 28 contiguous floats -> 7x STG.128.
__device__ __noinline__ void do_epilogue_pair(
    const float* __restrict__ sc, const float* __restrict__ sxa,
    const float* __restrict__ spos,
    float a00, float a01, float d0, int tp0,
    float a10, float a11, float d1, int tp1,
    float* __restrict__ op)
{
    __align__(16) float ob[28];
    epi_one(sc, sxa, spos, a00, a01, d0, tp0, ob);
    epi_one(sc, sxa, spos, a10, a11, d1, tp1, ob + 14);
    float4* dst = reinterpret_cast<float4*>(op);
    const float4* src = reinterpret_cast<const float4*>(ob);
#pragma unroll
    for (int i = 0; i < 7; i++)
        dst[i] = src[i];
}

// per-pair update (wls_j = L[s][t_j] * w_s precomputed per row)
#define PAIR_UPDATE(j, WLS)                                                    \
    {                                                                          \
        float e = fexp2(w_t[j] * (WLS));                                       \
        den[j]  += e;                                                          \
        acc0[j] = fmaf(e, wu.y, acc0[j]);                                      \
        acc1[j] = fmaf(e, wu.z, acc1[j]);                                      \
    }

// load one s-row: per-thread wu (rr,u0,u1) + warp-uniform L block
#define LOAD_ROW(sidx, c, tcol)                                                \
    float4 wu = *reinterpret_cast<const float4*>(s_wu + (((sidx)*NV)+(c))*4);  \
    const float* Lr = s_L + (sidx)*LT + (tcol);                                \
    float4 L0 = *reinterpret_cast<const float4*>(Lr);                          \
    float4 L1 = *reinterpret_cast<const float4*>(Lr + 4);                      \
    float wls0 = L0.x*wu.x, wls1 = L0.y*wu.x, wls2 = L0.z*wu.x, wls3 = L0.w*wu.x; \
    float wls4 = L1.x*wu.x, wls5 = L1.y*wu.x, wls6 = L1.z*wu.x, wls7 = L1.w*wu.x;

__global__ __launch_bounds__(256, 3) void micro_tf_kernel(
    const int*   __restrict__ idx,
    const float* __restrict__ tok_emb,
    const float* __restrict__ p_amp,   const float* __restrict__ p_phase,
    const float* __restrict__ p_slope, const float* __restrict__ p_offset,
    const float* __restrict__ p_cs,    const float* __restrict__ p_ci,
    const float* __restrict__ z_hi,    const float* __restrict__ special,
    const float* __restrict__ q_w,     const float* __restrict__ v_w,
    const float* __restrict__ out_A,   const float* __restrict__ out_B,
    const float* __restrict__ q_phase,
    const float* __restrict__ ln1_w,   const float* __restrict__ ln2_w,
    const float* __restrict__ lnf_w,
    const float* __restrict__ fc1_w,   const float* __restrict__ fc1_b,
    const float* __restrict__ fc2_w,   const float* __restrict__ fc2_b,
    const float* __restrict__ head_w,
    float* __restrict__ out, int B)
{
    __shared__ __align__(16) float s_wu[NROW * 4];   // {rr, u0, u1, 0} per (s,a)
    __shared__ __align__(16) float s_L[TT * LT];     // L[s][t] transposed, pre-scaled
    __shared__ __align__(16) float s_pos[TT * 4];
    __shared__ float s_xa[NV * 2];
    __shared__ float s_qh[TT * 5];
    __shared__ float s_qr[TT * 5];
    __shared__ __align__(16) float s_c[152];

    const int tid = threadIdx.x;

    // ---- stage A: per-t pos / q-hat / q-hat-rot ----
    if (tid < TT) {
        const int t = tid;
        float p0, p1, p2;
        if (t == 33)      { p0 = 0.f;        p1 = 0.f;        p2 = 0.f; }
        else if (t == 32) { p0 = z_hi[0];    p1 = z_hi[1];    p2 = z_hi[2]; }
        else if (t == 10) { p0 = special[0]; p1 = special[1]; p2 = special[2]; }
        else if (t == 21) { p0 = special[3]; p1 = special[4]; p2 = special[5]; }
        else {
            int i = (t < 10) ? t : ((t < 21) ? t - 11 : t - 22);
            float fi  = (float)i;
            float ang = 0.62831853071795864f * fi + p_phase[0];
            float amp = p_amp[0];
            float b0 = amp * cosf(ang);
            float b1 = amp * sinf(ang);
            float b2 = p_slope[0] * fi + p_offset[0];
            float m  = 1.0f + p_ci[0] + p_cs[0] * fi;
            p0 = b0 * m; p1 = b1 * m; p2 = b2 * m;
        }
        s_pos[t*4] = p0; s_pos[t*4+1] = p1; s_pos[t*4+2] = p2; s_pos[t*4+3] = 0.f;

        float hp0 = p0 * ln1_w[2], hp1 = p1 * ln1_w[3], hp2 = p2 * ln1_w[4];
        float qh[5];
#pragma unroll
        for (int d = 0; d < 5; d++)
            qh[d] = hp0*q_w[d*3] + hp1*q_w[d*3+1] + hp2*q_w[d*3+2];
        float cc = cosf(q_phase[0]), ss = sinf(q_phase[0]);
        s_qh[t*5+0] = qh[0]; s_qh[t*5+1] = qh[1]; s_qh[t*5+2] = qh[2];
        s_qh[t*5+3] = qh[3]; s_qh[t*5+4] = qh[4];
        s_qr[t*5+0] = qh[0]*cc - qh[1]*ss;
        s_qr[t*5+1] = qh[0]*ss + qh[1]*cc;
        s_qr[t*5+2] = qh[2]*cc - qh[3]*ss;
        s_qr[t*5+3] = qh[2]*ss + qh[3]*cc;
        s_qr[t*5+4] = qh[4];
    }
    if (tid < NV * 2) s_xa[tid] = tok_emb[tid];

    if (tid == 0) {
        // G[c][j] = sum_d v_w[d*2+c] * (out_A@out_B)[d][j]
        float M1[25];
        for (int d = 0; d < 5; d++)
            for (int j = 0; j < 5; j++)
                M1[d*5 + j] = out_A[d*2]*out_B[j] + out_A[d*2+1]*out_B[5+j];
        for (int c = 0; c < 2; c++)
            for (int j = 0; j < 5; j++) {
                float g = 0.f;
                for (int d = 0; d < 5; d++) g += v_w[d*2 + c] * M1[d*5 + j];
                s_c[c*5 + j] = g;
            }
        for (int j = 0; j < 5; j++)
            for (int v = 0; v < NV; v++)
                s_c[28 + j*16 + v] =
                    lnf_w[j] * (head_w[j]*tok_emb[v*2] + head_w[5+j]*tok_emb[v*2+1]);
        for (int f = 0; f < 2; f++)
            for (int j = 0; j < 5; j++)
                s_c[108 + f*5 + j] = fc1_w[f*5 + j] * ln2_w[j];
        s_c[118] = fc1_b[0]; s_c[119] = fc1_b[1];
        for (int d = 0; d < 5; d++) {
            s_c[120 + d*2]     = fc2_w[d*2];
            s_c[120 + d*2 + 1] = fc2_w[d*2 + 1];
            s_c[130 + d]       = fc2_b[d];
        }
    }
    __syncthreads();

    // ---- stage B: wu per (s,a) ----
    for (int r = tid; r < TT * NV; r += 256) {
        int t = r / NV, a = r % NV;
        float x0 = s_xa[a*2], x1 = s_xa[a*2+1];
        float p0 = s_pos[t*4], p1 = s_pos[t*4+1], p2 = s_pos[t*4+2];
        float ms = (x0*x0 + x1*x1 + p0*p0 + p1*p1 + p2*p2) * 0.2f;
        float rr = rsqrtf(ms + 1e-5f);
        s_wu[r*4]   = rr;
        s_wu[r*4+1] = rr * x0 * ln1_w[0];
        s_wu[r*4+2] = rr * x1 * ln1_w[1];
        s_wu[r*4+3] = 0.f;
    }

    // ---- stage C: transposed L[s][t] = ksc * qr(t).qh(s) ----
    const float ksc = 1.4426950408889634f * 0.44721359549995794f; // log2e/sqrt5
    for (int r = tid; r < TT * TT; r += 256) {
        int s = r / TT, t = r % TT;
        float l = s_qr[t*5]*s_qh[s*5] + s_qr[t*5+1]*s_qh[s*5+1]
                + s_qr[t*5+2]*s_qh[s*5+2] + s_qr[t*5+3]*s_qh[s*5+3]
                + s_qr[t*5+4]*s_qh[s*5+4];
        s_L[s*LT + t] = l * ksc;
    }
    __syncthreads();

    const int b = blockIdx.x * 256 + tid;
    if (b >= B) return;

    // ---- pack this row's 34 tokens, 4 bits each ----
    uint32_t pk[5] = {0u, 0u, 0u, 0u, 0u};
    const int2* ip2 = reinterpret_cast<const int2*>(idx + (size_t)b * TT);
#pragma unroll
    for (int w = 0; w < 17; w++) {
        int2 tv = __ldg(ip2 + w);
        const int s0 = 2*w, s1 = 2*w + 1;
        pk[s0 >> 3] |= ((uint32_t)tv.x) << ((s0 & 7) * 4);
        pk[s1 >> 3] |= ((uint32_t)tv.y) << ((s1 & 7) * 4);
    }

    float* obase = out + (size_t)b * (TT * NV);

    float w_t[8], acc0[8], acc1[8], den[8];

#pragma unroll
    for (int k = 0; k < 5; k++) {
        const int nt = (k == 4) ? 2 : 8;
        const uint32_t tb = pk[k];
        const int tcol = 8 * k;

        // per-tile query weights, zero accumulators
#pragma unroll
        for (int j = 0; j < 8; j++) {
            if (j < nt) {
                int a = (tb >> (4*j)) & 15;
                w_t[j] = s_wu[(((tcol + j) * NV) + a) * 4];
                den[j] = 0.f; acc0[j] = 0.f; acc1[j] = 0.f;
            }
        }

        // phase 1: full octets s in [0, 8k)
#pragma unroll
        for (int w = 0; w < k; w++) {
            uint32_t bits = pk[w];
#pragma unroll 1
            for (int jj = 0; jj < 8; jj++) {
                int c = bits & 15; bits >>= 4;
                LOAD_ROW(w*8 + jj, c, tcol)
                if (nt == 8) {
                    PAIR_UPDATE(0, wls0) PAIR_UPDATE(1, wls1)
                    PAIR_UPDATE(2, wls2) PAIR_UPDATE(3, wls3)
                    PAIR_UPDATE(4, wls4) PAIR_UPDATE(5, wls5)
                    PAIR_UPDATE(6, wls6) PAIR_UPDATE(7, wls7)
                } else {
                    PAIR_UPDATE(0, wls0) PAIR_UPDATE(1, wls1)
                    (void)wls2; (void)wls3; (void)wls4;
                    (void)wls5; (void)wls6; (void)wls7;
                }
            }
        }

        // phase 2: triangular, s = 8k + s2 (query j active iff j >= s2)
        {
            uint32_t bits = tb;
#pragma unroll
            for (int s2 = 0; s2 < 8; s2++) {
                if (s2 < nt) {
                    int c = bits & 15;
                    LOAD_ROW(tcol + s2, c, tcol)
                    if (s2 <= 0 && 0 < nt) PAIR_UPDATE(0, wls0)
                    if (s2 <= 1 && 1 < nt) PAIR_UPDATE(1, wls1)
                    if (s2 <= 2 && 2 < nt) PAIR_UPDATE(2, wls2)
                    if (s2 <= 3 && 3 < nt) PAIR_UPDATE(3, wls3)
                    if (s2 <= 4 && 4 < nt) PAIR_UPDATE(4, wls4)
                    if (s2 <= 5 && 5 < nt) PAIR_UPDATE(5, wls5)
                    if (s2 <= 6 && 6 < nt) PAIR_UPDATE(6, wls6)
                    if (s2 <= 7 && 7 < nt) PAIR_UPDATE(7, wls7)
                }
                bits >>= 4;
            }
        }

        // epilogue per pair of t's (noinline) -> 7x STG.128 per pair
#pragma unroll
        for (int jp = 0; jp < 4; jp++) {
            const int j0 = 2*jp, j1 = 2*jp + 1;
            if (j0 < nt) {
                int t0 = tcol + j0, t1 = tcol + j1;
                int a0 = (tb >> (4*j0)) & 15;
                int a1 = (tb >> (4*j1)) & 15;
                do_epilogue_pair(s_c, s_xa, s_pos,
                    acc0[j0], acc1[j0], den[j0], t0*16 + a0,
                    acc0[j1], acc1[j1], den[j1], t1*16 + a1,
                    obase + t0 * NV);
            }
        }
    }
}

extern "C" void kernel_launch(void* const* d_in, const int* in_sizes, int n_in,
                              void* d_out, int out_size)
{
    const int*   idx     = (const int*)  d_in[0];
    const float* tok_emb = (const float*)d_in[1];
    const float* amp     = (const float*)d_in[2];
    const float* phase   = (const float*)d_in[3];
    const float* slope   = (const float*)d_in[4];
    const float* offset  = (const float*)d_in[5];
    const float* cslope  = (const float*)d_in[6];
    const float* cicept  = (const float*)d_in[7];
    const float* z_hi    = (const float*)d_in[8];
    const float* special = (const float*)d_in[9];
    const float* q_w     = (const float*)d_in[10];
    const float* v_w     = (const float*)d_in[11];
    const float* out_A   = (const float*)d_in[12];
    const float* out_B   = (const float*)d_in[13];
    const float* q_phase = (const float*)d_in[14];
    const float* ln1_w   = (const float*)d_in[15];
    const float* ln2_w   = (const float*)d_in[16];
    const float* lnf_w   = (const float*)d_in[17];
    const float* fc1_w   = (const float*)d_in[18];
    const float* fc1_b   = (const float*)d_in[19];
    const float* fc2_w   = (const float*)d_in[20];
    const float* fc2_b   = (const float*)d_in[21];
    const float* head_w  = (const float*)d_in[22];
    float* out = (float*)d_out;

    const int B = in_sizes[0] / TT;
    dim3 grid((B + 255) / 256);
    micro_tf_kernel<<<grid, 256>>>(
        idx, tok_emb, amp, phase, slope, offset, cslope, cicept,
        z_hi, special, q_w, v_w, out_A, out_B, q_phase,
        ln1_w, ln2_w, lnf_w, fc1_w, fc1_b, fc2_w, fc2_b, head_w,
        out, B);
}

// round 16
// speedup vs baseline: 1.0835x; 1.0790x over previous
#include <cuda_runtime.h>
#include <math.h>
#include <stdint.h>

#define TT 34
#define NV 14
#define NROW (TT * NV)      // 476
#define LT 40               // transposed L-table row stride (floats)

// -------- fast approx intrinsics -----
__device__ __forceinline__ float fexp2(float x) {
    float r; asm("ex2.approx.f32 %0, %1;" : "=f"(r) : "f"(x)); return r;
}
__device__ __forceinline__ float frsq(float x) {
    float r; asm("rsqrt.approx.f32 %0, %1;" : "=f"(r) : "f"(x)); return r;
}
__device__ __forceinline__ float frcp(float x) {
    float r; asm("rcp.approx.f32 %0, %1;" : "=f"(r) : "f"(x)); return r;
}

// ----------------------------------------------------------------------------
// Epilogue for ONE t (scalar). tp = t*16 + a.
// sc: [0..9] G (2x5 fold of V^T@out_A@out_B) | [28+j*16+v] W' | [108..117] F1
//     [118..119] fc1_b | [120..129] fc2_w | [130..134] fc2_b
// ----------------------------------------------------------------------------
__device__ __forceinline__ void epi_one(
    const float* __restrict__ sc, const float* __restrict__ sxa,
    const float* __restrict__ spos,
    float a0, float a1, float den, int tp, float* __restrict__ ob)
{
    const int t = tp >> 4, a = tp & 15;
    float x0 = sxa[a*2], x1 = sxa[a*2+1];
    float x2 = spos[t*4], x3 = spos[t*4+1], x4 = spos[t*4+2];

    float inv = frcp(den);
    float A0 = a0 * inv, A1 = a1 * inv;

    float y0 = x0 + A0*sc[0] + A1*sc[5];
    float y1 = x1 + A0*sc[1] + A1*sc[6];
    float y2 = x2 + A0*sc[2] + A1*sc[7];
    float y3 = x3 + A0*sc[3] + A1*sc[8];
    float y4 = x4 + A0*sc[4] + A1*sc[9];

    float r2 = frsq((y0*y0 + y1*y1 + y2*y2 + y3*y3 + y4*y4) * 0.2f + 1e-5f);

    float g0 = fmaf(r2, y0*sc[108] + y1*sc[109] + y2*sc[110] + y3*sc[111] + y4*sc[112], sc[118]);
    float g1 = fmaf(r2, y0*sc[113] + y1*sc[114] + y2*sc[115] + y3*sc[116] + y4*sc[117], sc[119]);

    const float isq2 = 0.70710678118654752f;
    float e0 = 0.5f * g0 * (1.0f + erff(g0 * isq2));
    float e1 = 0.5f * g1 * (1.0f + erff(g1 * isq2));

    float z0 = y0 + sc[130] + e0*sc[120] + e1*sc[121];
    float z1 = y1 + sc[131] + e0*sc[122] + e1*sc[123];
    float z2 = y2 + sc[132] + e0*sc[124] + e1*sc[125];
    float z3 = y3 + sc[133] + e0*sc[126] + e1*sc[127];
    float z4 = y4 + sc[134] + e0*sc[128] + e1*sc[129];

    float rf = frsq((z0*z0 + z1*z1 + z2*z2 + z3*z3 + z4*z4) * 0.2f + 1e-5f);
    z0 *= rf; z1 *= rf; z2 *= rf; z3 *= rf; z4 *= rf;

#pragma unroll
    for (int v = 0; v < NV; v++) {
        ob[v] = z0*sc[28 + v] + z1*sc[44 + v] + z2*sc[60 + v]
              + z3*sc[76 + v] + z4*sc[92 + v];
    }
}

// Pair epilogue: two consecutive t's -> 28 contiguous floats -> 7x STG.128.
__device__ __noinline__ void do_epilogue_pair(
    const float* __restrict__ sc, const float* __restrict__ sxa,
    const float* __restrict__ spos,
    float a00, float a01, float d0, int tp0,
    float a10, float a11, float d1, int tp1,
    float* __restrict__ op)
{
    __align__(16) float ob[28];
    epi_one(sc, sxa, spos, a00, a01, d0, tp0, ob);
    epi_one(sc, sxa, spos, a10, a11, d1, tp1, ob + 14);
    float4* dst = reinterpret_cast<float4*>(op);
    const float4* src = reinterpret_cast<const float4*>(ob);
#pragma unroll
    for (int i = 0; i < 7; i++)
        dst[i] = src[i];
}

// per-pair update
#define PAIR_UPDATE(j, WLS)                                                    \
    {                                                                          \
        float e = fexp2(w_t[j] * (WLS));                                       \
        den[j]  += e;                                                          \
        acc0[j] = fmaf(e, wu.y, acc0[j]);                                      \
        acc1[j] = fmaf(e, wu.z, acc1[j]);                                      \
    }

// load one s-row for a 4-wide tile: wu (rr,u0,u1) + one float4 of L
#define LOAD_ROW4(sidx, c, tcol)                                               \
    float4 wu = *reinterpret_cast<const float4*>(s_wu + (((sidx)*NV)+(c))*4);  \
    float4 L0 = *reinterpret_cast<const float4*>(s_L + (sidx)*LT + (tcol));    \
    float wls0 = L0.x*wu.x, wls1 = L0.y*wu.x, wls2 = L0.z*wu.x, wls3 = L0.w*wu.x;

// One 4-wide t-tile: queries t = tbase .. tbase+nt-1
template <int K>
__device__ __forceinline__ void run_tile(
    const uint32_t (&pk)[5],
    const float* __restrict__ s_wu, const float* __restrict__ s_L,
    const float* __restrict__ s_c,  const float* __restrict__ s_xa,
    const float* __restrict__ s_pos, float* __restrict__ obase)
{
    constexpr int tbase = 4 * K;
    constexpr int nt    = (tbase + 4 <= TT) ? 4 : (TT - tbase);
    const uint32_t tb = pk[tbase >> 3] >> ((tbase & 7) * 4);

    float w_t[4], acc0[4], acc1[4], den[4];

#pragma unroll
    for (int j = 0; j < nt; j++) {
        int a = (tb >> (4*j)) & 15;
        w_t[j] = s_wu[(((tbase + j) * NV) + a) * 4];
        den[j] = 0.f; acc0[j] = 0.f; acc1[j] = 0.f;
    }

    // full part: s in [0, tbase)
    constexpr int FW = tbase >> 3;
#pragma unroll
    for (int w = 0; w < FW; w++) {
        uint32_t bits = pk[w];
#pragma unroll 1
        for (int jj = 0; jj < 8; jj++) {
            int c = bits & 15; bits >>= 4;
            LOAD_ROW4(w*8 + jj, c, tbase)
            PAIR_UPDATE(0, wls0)
            PAIR_UPDATE(1, wls1)
            if (nt == 4) { PAIR_UPDATE(2, wls2) PAIR_UPDATE(3, wls3) }
            else { (void)wls2; (void)wls3; }
        }
    }
    if constexpr ((tbase & 7) != 0) {   // 4 leftover nibbles
        uint32_t bits = pk[FW];
#pragma unroll
        for (int jj = 0; jj < 4; jj++) {
            int c = bits & 15; bits >>= 4;
            LOAD_ROW4(FW*8 + jj, c, tbase)
            PAIR_UPDATE(0, wls0)
            PAIR_UPDATE(1, wls1)
            if (nt == 4) { PAIR_UPDATE(2, wls2) PAIR_UPDATE(3, wls3) }
            else { (void)wls2; (void)wls3; }
        }
    }

    // triangular part: s = tbase + jj, queries j >= jj
    {
        uint32_t bits = tb;
#pragma unroll
        for (int jj = 0; jj < nt; jj++) {
            int c = bits & 15; bits >>= 4;
            LOAD_ROW4(tbase + jj, c, tbase)
            if (jj <= 0) PAIR_UPDATE(0, wls0)
            if (jj <= 1) PAIR_UPDATE(1, wls1)
            if (nt == 4) {
                if (jj <= 2) PAIR_UPDATE(2, wls2)
                PAIR_UPDATE(3, wls3)
            } else { (void)wls2; (void)wls3; }
        }
    }

    // epilogue per pair of t's
#pragma unroll
    for (int jp = 0; jp < 2; jp++) {
        const int j0 = 2*jp, j1 = 2*jp + 1;
        if (j0 < nt) {
            int t0 = tbase + j0, t1 = tbase + j1;
            int a0 = (tb >> (4*j0)) & 15;
            int a1 = (tb >> (4*j1)) & 15;
            do_epilogue_pair(s_c, s_xa, s_pos,
                acc0[j0], acc1[j0], den[j0], t0*16 + a0,
                acc0[j1], acc1[j1], den[j1], t1*16 + a1,
                obase + t0 * NV);
        }
    }
}

__global__ __launch_bounds__(256, 3) void micro_tf_kernel(
    const int*   __restrict__ idx,
    const float* __restrict__ tok_emb,
    const float* __restrict__ p_amp,   const float* __restrict__ p_phase,
    const float* __restrict__ p_slope, const float* __restrict__ p_offset,
    const float* __restrict__ p_cs,    const float* __restrict__ p_ci,
    const float* __restrict__ z_hi,    const float* __restrict__ special,
    const float* __restrict__ q_w,     const float* __restrict__ v_w,
    const float* __restrict__ out_A,   const float* __restrict__ out_B,
    const float* __restrict__ q_phase,
    const float* __restrict__ ln1_w,   const float* __restrict__ ln2_w,
    const float* __restrict__ lnf_w,
    const float* __restrict__ fc1_w,   const float* __restrict__ fc1_b,
    const float* __restrict__ fc2_w,   const float* __restrict__ fc2_b,
    const float* __restrict__ head_w,
    float* __restrict__ out, int B)
{
    __shared__ __align__(16) float s_wu[NROW * 4];
    __shared__ __align__(16) float s_L[TT * LT];
    __shared__ __align__(16) float s_pos[TT * 4];
    __shared__ float s_xa[NV * 2];
    __shared__ float s_qh[TT * 5];
    __shared__ float s_qr[TT * 5];
    __shared__ __align__(16) float s_c[152];

    const int tid = threadIdx.x;

    // ---- stage A: per-t pos / q-hat / q-hat-rot ----
    if (tid < TT) {
        const int t = tid;
        float p0, p1, p2;
        if (t == 33)      { p0 = 0.f;        p1 = 0.f;        p2 = 0.f; }
        else if (t == 32) { p0 = z_hi[0];    p1 = z_hi[1];    p2 = z_hi[2]; }
        else if (t == 10) { p0 = special[0]; p1 = special[1]; p2 = special[2]; }
        else if (t == 21) { p0 = special[3]; p1 = special[4]; p2 = special[5]; }
        else {
            int i = (t < 10) ? t : ((t < 21) ? t - 11 : t - 22);
            float fi  = (float)i;
            float ang = 0.62831853071795864f * fi + p_phase[0];
            float amp = p_amp[0];
            float b0 = amp * cosf(ang);
            float b1 = amp * sinf(ang);
            float b2 = p_slope[0] * fi + p_offset[0];
            float m  = 1.0f + p_ci[0] + p_cs[0] * fi;
            p0 = b0 * m; p1 = b1 * m; p2 = b2 * m;
        }
        s_pos[t*4] = p0; s_pos[t*4+1] = p1; s_pos[t*4+2] = p2; s_pos[t*4+3] = 0.f;

        float hp0 = p0 * ln1_w[2], hp1 = p1 * ln1_w[3], hp2 = p2 * ln1_w[4];
        float qh[5];
#pragma unroll
        for (int d = 0; d < 5; d++)
            qh[d] = hp0*q_w[d*3] + hp1*q_w[d*3+1] + hp2*q_w[d*3+2];
        float cc = cosf(q_phase[0]), ss = sinf(q_phase[0]);
        s_qh[t*5+0] = qh[0]; s_qh[t*5+1] = qh[1]; s_qh[t*5+2] = qh[2];
        s_qh[t*5+3] = qh[3]; s_qh[t*5+4] = qh[4];
        s_qr[t*5+0] = qh[0]*cc - qh[1]*ss;
        s_qr[t*5+1] = qh[0]*ss + qh[1]*cc;
        s_qr[t*5+2] = qh[2]*cc - qh[3]*ss;
        s_qr[t*5+3] = qh[2]*ss + qh[3]*cc;
        s_qr[t*5+4] = qh[4];
    }
    if (tid < NV * 2) s_xa[tid] = tok_emb[tid];

    if (tid == 0) {
        float M1[25];
        for (int d = 0; d < 5; d++)
            for (int j = 0; j < 5; j++)
                M1[d*5 + j] = out_A[d*2]*out_B[j] + out_A[d*2+1]*out_B[5+j];
        for (int c = 0; c < 2; c++)
            for (int j = 0; j < 5; j++) {
                float g = 0.f;
                for (int d = 0; d < 5; d++) g += v_w[d*2 + c] * M1[d*5 + j];
                s_c[c*5 + j] = g;
            }
        for (int j = 0; j < 5; j++)
            for (int v = 0; v < NV; v++)
                s_c[28 + j*16 + v] =
                    lnf_w[j] * (head_w[j]*tok_emb[v*2] + head_w[5+j]*tok_emb[v*2+1]);
        for (int f = 0; f < 2; f++)
            for (int j = 0; j < 5; j++)
                s_c[108 + f*5 + j] = fc1_w[f*5 + j] * ln2_w[j];
        s_c[118] = fc1_b[0]; s_c[119] = fc1_b[1];
        for (int d = 0; d < 5; d++) {
            s_c[120 + d*2]     = fc2_w[d*2];
            s_c[120 + d*2 + 1] = fc2_w[d*2 + 1];
            s_c[130 + d]       = fc2_b[d];
        }
    }
    __syncthreads();

    // ---- stage B: wu per (s,a) ----
    for (int r = tid; r < TT * NV; r += 256) {
        int t = r / NV, a = r % NV;
        float x0 = s_xa[a*2], x1 = s_xa[a*2+1];
        float p0 = s_pos[t*4], p1 = s_pos[t*4+1], p2 = s_pos[t*4+2];
        float ms = (x0*x0 + x1*x1 + p0*p0 + p1*p1 + p2*p2) * 0.2f;
        float rr = rsqrtf(ms + 1e-5f);
        s_wu[r*4]   = rr;
        s_wu[r*4+1] = rr * x0 * ln1_w[0];
        s_wu[r*4+2] = rr * x1 * ln1_w[1];
        s_wu[r*4+3] = 0.f;
    }

    // ---- stage C: transposed L[s][t] ----
    const float ksc = 1.4426950408889634f * 0.44721359549995794f;
    for (int r = tid; r < TT * TT; r += 256) {
        int s = r / TT, t = r % TT;
        float l = s_qr[t*5]*s_qh[s*5] + s_qr[t*5+1]*s_qh[s*5+1]
                + s_qr[t*5+2]*s_qh[s*5+2] + s_qr[t*5+3]*s_qh[s*5+3]
                + s_qr[t*5+4]*s_qh[s*5+4];
        s_L[s*LT + t] = l * ksc;
    }
    __syncthreads();

    // parity split: warps 0-3 even tiles {0,2,4,6,8}; warps 4-7 odd {1,3,5,7}
    const int p = tid >> 7;                       // warp-uniform
    const int b = blockIdx.x * 128 + (tid & 127);
    if (b >= B) return;

    // ---- pack this row's 34 tokens, 4 bits each ----
    uint32_t pk[5] = {0u, 0u, 0u, 0u, 0u};
    const int2* ip2 = reinterpret_cast<const int2*>(idx + (size_t)b * TT);
#pragma unroll
    for (int w = 0; w < 17; w++) {
        int2 tv = __ldg(ip2 + w);
        const int s0 = 2*w, s1 = 2*w + 1;
        pk[s0 >> 3] |= ((uint32_t)tv.x) << ((s0 & 7) * 4);
        pk[s1 >> 3] |= ((uint32_t)tv.y) << ((s1 & 7) * 4);
    }

    float* obase = out + (size_t)b * (TT * NV);

    if (p == 0) {
        run_tile<0>(pk, s_wu, s_L, s_c, s_xa, s_pos, obase);
        run_tile<2>(pk, s_wu, s_L, s_c, s_xa, s_pos, obase);
        run_tile<4>(pk, s_wu, s_L, s_c, s_xa, s_pos, obase);
        run_tile<6>(pk, s_wu, s_L, s_c, s_xa, s_pos, obase);
        run_tile<8>(pk, s_wu, s_L, s_c, s_xa, s_pos, obase);
    } else {
        run_tile<1>(pk, s_wu, s_L, s_c, s_xa, s_pos, obase);
        run_tile<3>(pk, s_wu, s_L, s_c, s_xa, s_pos, obase);
        run_tile<5>(pk, s_wu, s_L, s_c, s_xa, s_pos, obase);
        run_tile<7>(pk, s_wu, s_L, s_c, s_xa, s_pos, obase);
    }
}

extern "C" void kernel_launch(void* const* d_in, const int* in_sizes, int n_in,
                              void* d_out, int out_size)
{
    const int*   idx     = (const int*)  d_in[0];
    const float* tok_emb = (const float*)d_in[1];
    const float* amp     = (const float*)d_in[2];
    const float* phase   = (const float*)d_in[3];
    const float* slope   = (const float*)d_in[4];
    const float* offset  = (const float*)d_in[5];
    const float* cslope  = (const float*)d_in[6];
    const float* cicept  = (const float*)d_in[7];
    const float* z_hi    = (const float*)d_in[8];
    const float* special = (const float*)d_in[9];
    const float* q_w     = (const float*)d_in[10];
    const float* v_w     = (const float*)d_in[11];
    const float* out_A   = (const float*)d_in[12];
    const float* out_B   = (const float*)d_in[13];
    const float* q_phase = (const float*)d_in[14];
    const float* ln1_w   = (const float*)d_in[15];
    const float* ln2_w   = (const float*)d_in[16];
    const float* lnf_w   = (const float*)d_in[17];
    const float* fc1_w   = (const float*)d_in[18];
    const float* fc1_b   = (const float*)d_in[19];
    const float* fc2_w   = (const float*)d_in[20];
    const float* fc2_b   = (const float*)d_in[21];
    const float* head_w  = (const float*)d_in[22];
    float* out = (float*)d_out;

    const int B = in_sizes[0] / TT;
    dim3 grid((B + 127) / 128);
    micro_tf_kernel<<<grid, 256>>>(
        idx, tok_emb, amp, phase, slope, offset, cslope, cicept,
        z_hi, special, q_w, v_w, out_A, out_B, q_phase,
        ln1_w, ln2_w, lnf_w, fc1_w, fc1_b, fc2_w, fc2_b, head_w,
        out, B);
}